// round 2
// baseline (speedup 1.0000x reference)
#include <cuda_runtime.h>

// RNN_64501818851829 — persistent fp32x2 SIMT RNN for GB300 (sm_103a)
//
// Shapes: B=4096 rows, T=1024 steps, hidden H=40, combined K1=41.
// Each block owns 16 rows (8 f32x2 "pairs") for the entire T loop.
// Weights are pre-duplicated f32x2 in shared memory ([k][j]-major) so the
// inner dot is: 1 LDS.64 (combined, broadcast) + 2 LDS.128 (4 dup weights)
// + 4 fma.rn.f32x2  => fma-pipe-bound at ~128 FMA/cyc/SM.

typedef unsigned long long u64;

static constexpr int Bn = 4096;
static constexpr int Tn = 1024;
static constexpr int PAIRS = 8;            // row-pairs per block (16 rows)
static constexpr int JG = 20;              // neuron groups (NJ=4 neurons each)
static constexpr int NTHR = PAIRS * JG;    // 160 threads
static constexpr int NBLK = (Bn / 2) / PAIRS;  // 256 blocks

// Scratch (no cudaMalloc allowed): transposed input [T][B] and output [T][B]
__device__ float g_uT[Tn * Bn];
__device__ float g_outT[Tn * Bn];

// ---------------- f32x2 helpers ----------------
__device__ __forceinline__ u64 fma2(u64 a, u64 b, u64 c) {
    u64 d; asm("fma.rn.f32x2 %0, %1, %2, %3;" : "=l"(d) : "l"(a), "l"(b), "l"(c));
    return d;
}
__device__ __forceinline__ u64 add2(u64 a, u64 b) {
    u64 d; asm("add.rn.f32x2 %0, %1, %2;" : "=l"(d) : "l"(a), "l"(b));
    return d;
}
__device__ __forceinline__ u64 mul2(u64 a, u64 b) {
    u64 d; asm("mul.rn.f32x2 %0, %1, %2;" : "=l"(d) : "l"(a), "l"(b));
    return d;
}
__device__ __forceinline__ u64 pack2(float lo, float hi) {
    u64 d; asm("mov.b64 %0, {%1, %2};" : "=l"(d) : "f"(lo), "f"(hi));
    return d;
}
__device__ __forceinline__ void unpack2(u64 v, float& lo, float& hi) {
    asm("mov.b64 {%0, %1}, %2;" : "=f"(lo), "=f"(hi) : "l"(v));
}
__device__ __forceinline__ u64 dup2(float x) { return pack2(x, x); }
__device__ __forceinline__ u64 lrelu2(u64 x) {
    float a, b; unpack2(x, a, b);
    a = fmaxf(a, 0.0f) + 0.01f * fminf(a, 0.0f);
    b = fmaxf(b, 0.0f) + 0.01f * fminf(b, 0.0f);
    return pack2(a, b);
}

// ---------------- transpose kernels ----------------
// in: inputs [B][T] -> g_uT [T][B]
__global__ void tpose_in_kernel(const float* __restrict__ src) {
    __shared__ float tile[32][33];
    int c0 = blockIdx.x * 32, r0 = blockIdx.y * 32;   // c over T, r over B
    int x = c0 + threadIdx.x;
#pragma unroll
    for (int i = threadIdx.y; i < 32; i += 8)
        tile[i][threadIdx.x] = src[(size_t)(r0 + i) * Tn + x];
    __syncthreads();
    int y = r0 + threadIdx.x;
#pragma unroll
    for (int i = threadIdx.y; i < 32; i += 8)
        g_uT[(size_t)(c0 + i) * Bn + y] = tile[threadIdx.x][i];
}

// out: g_outT [T][B] -> d_out [B][T]
__global__ void tpose_out_kernel(float* __restrict__ dst) {
    __shared__ float tile[32][33];
    int c0 = blockIdx.x * 32, r0 = blockIdx.y * 32;   // c over B, r over T
    int x = c0 + threadIdx.x;
#pragma unroll
    for (int i = threadIdx.y; i < 32; i += 8)
        tile[i][threadIdx.x] = g_outT[(size_t)(r0 + i) * Bn + x];
    __syncthreads();
    int y = r0 + threadIdx.x;
#pragma unroll
    for (int i = threadIdx.y; i < 32; i += 8)
        dst[(size_t)(c0 + i) * Tn + y] = tile[threadIdx.x][i];
}

// ---------------- main persistent RNN kernel ----------------
__global__ void __launch_bounds__(NTHR, 2) rnn_kernel(
    const float* __restrict__ w1,  const float* __restrict__ b1,
    const float* __restrict__ w2,  const float* __restrict__ b2,
    const float* __restrict__ ow1, const float* __restrict__ ob1,
    const float* __restrict__ ow2, const float* __restrict__ ob2)
{
    // L1 weights combined: j<40 -> h2h_w1 row j; j in [40,80) -> h2o_w1 row j-40
    __shared__ __align__(16) u64 shWc[41 * 80];       // [k][j] dup   26240 B
    __shared__ __align__(16) u64 shW2[40 * 40];       // [k][j] dup   12800 B
    __shared__ __align__(16) u64 shComb[PAIRS * 42];  // [p]: [1]=u, [2..41]=hidden
    __shared__ __align__(16) u64 shA[PAIRS * 42];     // h2h L1 activations
    __shared__ __align__(16) u64 shPart[PAIRS * 42];  // L2 upper-half partials
    __shared__ __align__(16) u64 shOutp[PAIRS * 12];  // output-dot partials (10)

    const int tid  = threadIdx.x;
    const int pair = tid & (PAIRS - 1);
    const int jg   = tid >> 3;          // 0..19
    const bool islo = (jg < 10);
    const int jj   = islo ? jg : jg - 10;
    const int n0   = 4 * jj;
    const int row0 = 2 * (blockIdx.x * PAIRS + pair);

    // Cooperative weight load with duplication into f32x2
    for (int idx = tid; idx < 41 * 80; idx += NTHR) {
        int k = idx / 80, j = idx % 80;
        float w = (j < 40) ? w1[j * 41 + k] : ow1[(j - 40) * 41 + k];
        shWc[idx] = dup2(w);
    }
    for (int idx = tid; idx < 40 * 40; idx += NTHR) {
        int k = idx / 40, j = idx % 40;
        shW2[idx] = dup2(w2[j * 40 + k]);
    }
    for (int idx = tid; idx < PAIRS * 42; idx += NTHR) shComb[idx] = 0ull;

    // Per-thread constants in registers
    u64 rb1[4], rX[4];
    if (islo) {
#pragma unroll
        for (int i = 0; i < 4; i++) { rb1[i] = dup2(b1[n0 + i]); rX[i] = dup2(b2[n0 + i]); }
    } else {
#pragma unroll
        for (int i = 0; i < 4; i++) { rb1[i] = dup2(ob1[n0 + i]); rX[i] = dup2(ow2[n0 + i]); }
    }
    const u64 bout = dup2(ob2[0]);

    __syncthreads();
    if (jg == 1) shComb[pair * 42 + 1] = *(const u64*)&g_uT[row0];  // u at t=0

    const u64* __restrict__ cb = shComb + pair * 42 + 1;
    const u64* __restrict__ ap = shA + pair * 42 + (islo ? 0 : 20);
    const u64* __restrict__ w2base = shW2 + (islo ? 0 : 20) * 40 + 4 * jj;

    u64 uNext = 0ull;
    for (int t = 0; t < Tn; t++) {
        __syncthreads();  // combined[t] ready

        // ---- L1: 80 neurons x dot-41 (this thread: 4 neurons) ----
        u64 a0 = rb1[0], a1 = rb1[1], a2 = rb1[2], a3 = rb1[3];
#pragma unroll
        for (int k = 0; k < 41; k++) {
            u64 c = cb[k];
            const ulonglong2* w = (const ulonglong2*)(shWc + k * 80 + 4 * jg);
            ulonglong2 wA = w[0], wB = w[1];
            a0 = fma2(c, wA.x, a0); a1 = fma2(c, wA.y, a1);
            a2 = fma2(c, wB.x, a2); a3 = fma2(c, wB.y, a3);
        }
        a0 = lrelu2(a0); a1 = lrelu2(a1); a2 = lrelu2(a2); a3 = lrelu2(a3);

        if (jg == 1)  // prefetch next step's input
            uNext = (t + 1 < Tn) ? *(const u64*)&g_uT[(t + 1) * Bn + row0] : 0ull;

        if (islo) {   // h2h activations -> shared for L2
            ulonglong2* d = (ulonglong2*)(shA + pair * 42 + 4 * jg);
            d[0] = make_ulonglong2(a0, a1);
            d[1] = make_ulonglong2(a2, a3);
        } else {      // h2o: local partial of the 40-wide output dot
            u64 s = mul2(a3, rX[3]);
            s = fma2(a2, rX[2], s);
            s = fma2(a1, rX[1], s);
            s = fma2(a0, rX[0], s);
            shOutp[pair * 12 + jj] = s;
        }
        __syncthreads();  // acts + out-partials ready

        // ---- L2: hidden_new (40 x dot-40), split lower/upper k halves ----
        u64 h0, h1, h2, h3;
        if (islo) { h0 = rX[0]; h1 = rX[1]; h2 = rX[2]; h3 = rX[3]; }
        else      { h0 = h1 = h2 = h3 = 0ull; }
#pragma unroll
        for (int k = 0; k < 20; k++) {
            u64 av = ap[k];
            const ulonglong2* w = (const ulonglong2*)(w2base + k * 40);
            ulonglong2 wA = w[0], wB = w[1];
            h0 = fma2(av, wA.x, h0); h1 = fma2(av, wA.y, h1);
            h2 = fma2(av, wB.x, h2); h3 = fma2(av, wB.y, h3);
        }
        if (!islo) {
            ulonglong2* d = (ulonglong2*)(shPart + pair * 42 + 4 * jj);
            d[0] = make_ulonglong2(h0, h1);
            d[1] = make_ulonglong2(h2, h3);
        }
        if (jg == 10) {  // reduce output partials, write out[t] for 2 rows
            u64 s = bout;
#pragma unroll
            for (int i = 0; i < 10; i++) s = add2(s, shOutp[pair * 12 + i]);
            *(u64*)&g_outT[t * Bn + row0] = s;
        }
        __syncthreads();  // upper partials ready

        if (islo) {       // combine halves -> hidden_new -> next combined
            const ulonglong2* q = (const ulonglong2*)(shPart + pair * 42 + 4 * jg);
            ulonglong2 q0 = q[0], q1 = q[1];
            ulonglong2* d = (ulonglong2*)(shComb + pair * 42 + 2 + 4 * jg);
            d[0] = make_ulonglong2(add2(h0, q0.x), add2(h1, q0.y));
            d[1] = make_ulonglong2(add2(h2, q1.x), add2(h3, q1.y));
        }
        if (jg == 1) shComb[pair * 42 + 1] = uNext;  // next u
    }
}

extern "C" void kernel_launch(void* const* d_in, const int* in_sizes, int n_in,
                              void* d_out, int out_size) {
    const float* inputs = (const float*)d_in[0];
    const float* w1  = (const float*)d_in[1];
    const float* b1  = (const float*)d_in[2];
    const float* w2  = (const float*)d_in[3];
    const float* b2  = (const float*)d_in[4];
    const float* ow1 = (const float*)d_in[5];
    const float* ob1 = (const float*)d_in[6];
    const float* ow2 = (const float*)d_in[7];
    const float* ob2 = (const float*)d_in[8];
    float* out = (float*)d_out;

    // 1) transpose inputs [B][T] -> g_uT [T][B]
    tpose_in_kernel<<<dim3(Tn / 32, Bn / 32), dim3(32, 8)>>>(inputs);
    // 2) persistent RNN over all T steps
    rnn_kernel<<<NBLK, NTHR>>>(w1, b1, w2, b2, ow1, ob1, ow2, ob2);
    // 3) transpose g_outT [T][B] -> out [B][T]
    tpose_out_kernel<<<dim3(Bn / 32, Tn / 32), dim3(32, 8)>>>(out);
}

// round 3
// speedup vs baseline: 1.3425x; 1.3425x over previous
#include <cuda_runtime.h>

// RNN_64501818851829 — single persistent fp32x2 kernel for GB300 (sm_103a).
// B=4096, T=1024, H=40, combined K=41 (u + 40 hidden).
// 128 blocks x 128 threads (4 warps -> exactly 1 per SMSP). Block owns 32 rows
// (16 f32x2 row-pairs) for all T steps. 2 __syncthreads per step.
//
// Phase A (L1, 80 neurons = h2h_w1 rows 0-39 + h2o_w1 rows 40-79):
//   thread (s1 = tid&7, jg1 = tid>>3) does 5 neurons x 2 pairs (s1, s1+8).
//   Weights k-paired + dup'd: per 2 k's -> 7 LDS.128, 20 fma.rn.f32x2.
// Phase B (L2 hidden_new, 40 neurons):
//   thread (s2 = tid&15, jg2 = tid>>4) does 5 neurons x 1 pair, k=0..39.

typedef unsigned long long u64;

static constexpr int Bn = 4096;
static constexpr int Tn = 1024;
static constexpr int NTHR = 128;
static constexpr int NBLK = 128;           // 32 rows per block

// shared layout in u64 units
static constexpr int OFF_WCP  = 0;                 // [20 kp][16 jg][10]  3200
static constexpr int OFF_WU   = OFF_WCP + 3200;    // [16 jg][6]            96
static constexpr int OFF_W2P  = OFF_WU + 96;       // [20 kp][8 jg][10]   1600
static constexpr int OFF_COMB = OFF_W2P + 1600;    // [2][16 pair][42]    1344
static constexpr int OFF_A    = OFF_COMB + 1344;   // [16 pair][42]        672
static constexpr int OFF_OUTP = OFF_A + 672;       // [16 pair][8]         128
static constexpr int SMEM_U64 = OFF_OUTP + 128;    // 7040 u64 = 56320 B
static constexpr int SMEM_BYTES = SMEM_U64 * 8;

__device__ __forceinline__ u64 fma2(u64 a, u64 b, u64 c) {
    u64 d; asm("fma.rn.f32x2 %0, %1, %2, %3;" : "=l"(d) : "l"(a), "l"(b), "l"(c));
    return d;
}
__device__ __forceinline__ u64 add2(u64 a, u64 b) {
    u64 d; asm("add.rn.f32x2 %0, %1, %2;" : "=l"(d) : "l"(a), "l"(b));
    return d;
}
__device__ __forceinline__ u64 mul2(u64 a, u64 b) {
    u64 d; asm("mul.rn.f32x2 %0, %1, %2;" : "=l"(d) : "l"(a), "l"(b));
    return d;
}
__device__ __forceinline__ u64 pack2(float lo, float hi) {
    u64 d; asm("mov.b64 %0, {%1, %2};" : "=l"(d) : "f"(lo), "f"(hi));
    return d;
}
__device__ __forceinline__ u64 dup2(float x) {
    u64 d; asm("mov.b64 %0, {%1, %1};" : "=l"(d) : "f"(x));
    return d;
}
// exact leaky-relu(0.01): max(x, 0.01x)
__device__ __forceinline__ u64 lrelu2(u64 x, u64 c001) {
    u64 m = mul2(x, c001);
    float2 xf = *(float2*)&x, mf = *(float2*)&m, r;
    r.x = fmaxf(xf.x, mf.x);
    r.y = fmaxf(xf.y, mf.y);
    return *(u64*)&r;
}

__global__ void __launch_bounds__(NTHR, 1) rnn_kernel(
    const float* __restrict__ inputs,
    const float* __restrict__ w1,  const float* __restrict__ b1,
    const float* __restrict__ w2,  const float* __restrict__ b2,
    const float* __restrict__ ow1, const float* __restrict__ ob1,
    const float* __restrict__ ow2, const float* __restrict__ ob2,
    float* __restrict__ outp)
{
    extern __shared__ __align__(16) u64 sm[];
    u64* sWcP  = sm + OFF_WCP;
    u64* sWu   = sm + OFF_WU;
    u64* sW2P  = sm + OFF_W2P;
    u64* sComb = sm + OFF_COMB;   // [buf][pair][k]: k 0..39 = h, 40 = u (stride 42)
    u64* sA    = sm + OFF_A;      // [pair][k] h2h activations (stride 42)
    u64* sOutP = sm + OFF_OUTP;   // [pair][g] h2o partial dots (stride 8)

    const int tid = threadIdx.x;
    const int baseRow = blockIdx.x * 32;

    // ---- weight staging (dup to f32x2, k-paired) ----
    // L1 hidden part: logical k 0..39 maps to w1/ow1 column k+1 (combined = [u, h]).
    for (int idx = tid; idx < 40 * 80; idx += NTHR) {
        int kk = idx / 80, j = idx % 80;
        float w = (j < 40) ? w1[j * 41 + kk + 1] : ow1[(j - 40) * 41 + kk + 1];
        sWcP[(kk >> 1) * 160 + (j / 5) * 10 + (j % 5) * 2 + (kk & 1)] = dup2(w);
    }
    // L1 u part: w1/ow1 column 0
    for (int j = tid; j < 80; j += NTHR) {
        float w = (j < 40) ? w1[j * 41] : ow1[(j - 40) * 41];
        sWu[(j / 5) * 6 + (j % 5)] = dup2(w);
    }
    // L2: w2[j][k]
    for (int idx = tid; idx < 40 * 40; idx += NTHR) {
        int k = idx / 40, j = idx % 40;
        sW2P[(k >> 1) * 80 + (j / 5) * 10 + (j % 5) * 2 + (k & 1)] = dup2(w2[j * 40 + k]);
    }
    // zero both combined buffers (hidden0 = 0)
    for (int idx = tid; idx < 2 * 16 * 42; idx += NTHR) sComb[idx] = 0ull;

    // ---- per-thread roles & constants ----
    const int s1  = tid & 7,  jg1 = tid >> 3;   // Phase A
    const int s2  = tid & 15, jg2 = tid >> 4;   // Phase B
    const bool isH2H = (jg1 < 8);
    const u64 c001 = dup2(0.01f);

    u64 bA[5], rW[5], bB[5];
#pragma unroll
    for (int i = 0; i < 5; i++) {
        int nA = (isH2H ? 5 * jg1 : 5 * (jg1 - 8)) + i;
        bA[i] = isH2H ? dup2(b1[nA]) : dup2(ob1[nA]);
        rW[i] = isH2H ? 0ull : dup2(ow2[5 * (jg1 - 8) + i]);
        bB[i] = dup2(b2[5 * jg2 + i]);
    }
    const u64 bo = dup2(ob2[0]);
    const int r0 = baseRow + 2 * (tid & 15);   // rows for tid<16 duties
    const int r1 = r0 + 1;

    __syncthreads();
    if (tid < 16)   // u at t=0 into buffer 0
        sComb[tid * 42 + 40] = pack2(inputs[(size_t)r0 * Tn], inputs[(size_t)r1 * Tn]);
    __syncthreads();

    const u64* wpA = sWcP + jg1 * 10;
    const u64* wuA = sWu + jg1 * 6;
    const u64* wpB = sW2P + jg2 * 10;

    int cur = 0;
    for (int t = 0; t < Tn; t++) {
        const u64* cbA = sComb + cur * (16 * 42) + s1 * 42;
        const u64* cbB = cbA + 8 * 42;

        // ---- Phase A: L1 (combined @ W1), 5 neurons x 2 pairs ----
        u64 aA0 = bA[0], aA1 = bA[1], aA2 = bA[2], aA3 = bA[3], aA4 = bA[4];
        u64 aB0 = bA[0], aB1 = bA[1], aB2 = bA[2], aB3 = bA[3], aB4 = bA[4];
#pragma unroll
        for (int kp = 0; kp < 20; kp++) {
            ulonglong2 ca = *(const ulonglong2*)(cbA + 2 * kp);
            ulonglong2 cb = *(const ulonglong2*)(cbB + 2 * kp);
            const ulonglong2* w = (const ulonglong2*)(wpA + kp * 160);
            ulonglong2 w0 = w[0], w1v = w[1], w2v = w[2], w3v = w[3], w4v = w[4];
            aA0 = fma2(ca.y, w0.y,  fma2(ca.x, w0.x,  aA0));
            aB0 = fma2(cb.y, w0.y,  fma2(cb.x, w0.x,  aB0));
            aA1 = fma2(ca.y, w1v.y, fma2(ca.x, w1v.x, aA1));
            aB1 = fma2(cb.y, w1v.y, fma2(cb.x, w1v.x, aB1));
            aA2 = fma2(ca.y, w2v.y, fma2(ca.x, w2v.x, aA2));
            aB2 = fma2(cb.y, w2v.y, fma2(cb.x, w2v.x, aB2));
            aA3 = fma2(ca.y, w3v.y, fma2(ca.x, w3v.x, aA3));
            aB3 = fma2(cb.y, w3v.y, fma2(cb.x, w3v.x, aB3));
            aA4 = fma2(ca.y, w4v.y, fma2(ca.x, w4v.x, aA4));
            aB4 = fma2(cb.y, w4v.y, fma2(cb.x, w4v.x, aB4));
        }
        {   // u term
            u64 ua = cbA[40], ub = cbB[40];
            ulonglong2 u01 = *(const ulonglong2*)(wuA);
            ulonglong2 u23 = *(const ulonglong2*)(wuA + 2);
            u64 u4 = wuA[4];
            aA0 = fma2(ua, u01.x, aA0); aB0 = fma2(ub, u01.x, aB0);
            aA1 = fma2(ua, u01.y, aA1); aB1 = fma2(ub, u01.y, aB1);
            aA2 = fma2(ua, u23.x, aA2); aB2 = fma2(ub, u23.x, aB2);
            aA3 = fma2(ua, u23.y, aA3); aB3 = fma2(ub, u23.y, aB3);
            aA4 = fma2(ua, u4,    aA4); aB4 = fma2(ub, u4,    aB4);
        }
        aA0 = lrelu2(aA0, c001); aB0 = lrelu2(aB0, c001);
        aA1 = lrelu2(aA1, c001); aB1 = lrelu2(aB1, c001);
        aA2 = lrelu2(aA2, c001); aB2 = lrelu2(aB2, c001);
        aA3 = lrelu2(aA3, c001); aB3 = lrelu2(aB3, c001);
        aA4 = lrelu2(aA4, c001); aB4 = lrelu2(aB4, c001);

        if (isH2H) {  // store h2h activations
            u64* dA = sA + s1 * 42 + 5 * jg1;
            u64* dB = sA + (s1 + 8) * 42 + 5 * jg1;
            dA[0] = aA0; dA[1] = aA1; dA[2] = aA2; dA[3] = aA3; dA[4] = aA4;
            dB[0] = aB0; dB[1] = aB1; dB[2] = aB2; dB[3] = aB3; dB[4] = aB4;
        } else {      // h2o partial output dots
            u64 pa = mul2(aA0, rW[0]);
            pa = fma2(aA1, rW[1], pa); pa = fma2(aA2, rW[2], pa);
            pa = fma2(aA3, rW[3], pa); pa = fma2(aA4, rW[4], pa);
            u64 pb = mul2(aB0, rW[0]);
            pb = fma2(aB1, rW[1], pb); pb = fma2(aB2, rW[2], pb);
            pb = fma2(aB3, rW[3], pb); pb = fma2(aB4, rW[4], pb);
            sOutP[s1 * 8 + (jg1 - 8)] = pa;
            sOutP[(s1 + 8) * 8 + (jg1 - 8)] = pb;
        }

        u64 uN = 0ull;
        if (tid < 16 && t + 1 < Tn)   // prefetch next step's input
            uN = pack2(inputs[(size_t)r0 * Tn + t + 1], inputs[(size_t)r1 * Tn + t + 1]);

        __syncthreads();

        // ---- Phase B: L2 hidden_new (acts @ W2), 5 neurons x 1 pair ----
        const u64* ap = sA + s2 * 42;
        u64 h0 = bB[0], h1 = bB[1], h2 = bB[2], h3 = bB[3], h4 = bB[4];
#pragma unroll
        for (int kp = 0; kp < 20; kp++) {
            ulonglong2 av = *(const ulonglong2*)(ap + 2 * kp);
            const ulonglong2* w = (const ulonglong2*)(wpB + kp * 80);
            ulonglong2 w0 = w[0], w1v = w[1], w2v = w[2], w3v = w[3], w4v = w[4];
            h0 = fma2(av.y, w0.y,  fma2(av.x, w0.x,  h0));
            h1 = fma2(av.y, w1v.y, fma2(av.x, w1v.x, h1));
            h2 = fma2(av.y, w2v.y, fma2(av.x, w2v.x, h2));
            h3 = fma2(av.y, w3v.y, fma2(av.x, w3v.x, h3));
            h4 = fma2(av.y, w4v.y, fma2(av.x, w4v.x, h4));
        }
        u64* dst = sComb + (cur ^ 1) * (16 * 42) + s2 * 42 + 5 * jg2;
        dst[0] = h0; dst[1] = h1; dst[2] = h2; dst[3] = h3; dst[4] = h4;

        if (tid < 16) {  // reduce h2o partials -> out[t], stash next u
            const ulonglong2* pp = (const ulonglong2*)(sOutP + tid * 8);
            ulonglong2 p0 = pp[0], p1 = pp[1], p2 = pp[2], p3 = pp[3];
            u64 s = add2(add2(add2(p0.x, p0.y), add2(p1.x, p1.y)),
                         add2(add2(p2.x, p2.y), add2(p3.x, p3.y)));
            s = add2(s, bo);
            float2 sf = *(float2*)&s;
            outp[(size_t)r0 * Tn + t] = sf.x;
            outp[(size_t)r1 * Tn + t] = sf.y;
            sComb[(cur ^ 1) * (16 * 42) + tid * 42 + 40] = uN;
        }
        __syncthreads();
        cur ^= 1;
    }
}

extern "C" void kernel_launch(void* const* d_in, const int* in_sizes, int n_in,
                              void* d_out, int out_size) {
    const float* inputs = (const float*)d_in[0];
    const float* w1  = (const float*)d_in[1];
    const float* b1  = (const float*)d_in[2];
    const float* w2  = (const float*)d_in[3];
    const float* b2  = (const float*)d_in[4];
    const float* ow1 = (const float*)d_in[5];
    const float* ob1 = (const float*)d_in[6];
    const float* ow2 = (const float*)d_in[7];
    const float* ob2 = (const float*)d_in[8];
    float* out = (float*)d_out;

    cudaFuncSetAttribute(rnn_kernel, cudaFuncAttributeMaxDynamicSharedMemorySize,
                         SMEM_BYTES);
    rnn_kernel<<<NBLK, NTHR, SMEM_BYTES>>>(inputs, w1, b1, w2, b2,
                                           ow1, ob1, ow2, ob2, out);
}